// round 7
// baseline (speedup 1.0000x reference)
#include <cuda_runtime.h>
#include <cuda_bf16.h>

#define BB 512
#define TT 512
#define LL 64
#define NTHR 128                     // 2 threads per label: tid = 2*j + h
#define PSTRIDE 68                   // padded p-row (float) to avoid bank conflicts

__device__ float g_res[BB];
__device__ unsigned int g_done = 0;  // last-CTA ticket (self-resetting)

__global__ void __launch_bounds__(NTHR) crf_main_kernel(
    const float* __restrict__ emission,   // [B,T,L]
    const int*   __restrict__ target,     // [B,T]
    const float* __restrict__ mask,       // [B,T]
    const float* __restrict__ start_trans,// [L]
    const float* __restrict__ trans,      // [L,L]
    const float* __restrict__ end_trans,  // [L]
    float* __restrict__ out)
{
    __shared__ float2 sm_me[TT];                         // (mask, endmask)
    __shared__ __align__(16) float sm_p[2][PSTRIDE];     // padded, double-buffered
    __shared__ float sm_s0[2];
    __shared__ float sm_w[4];
    __shared__ float sm_w2[4];
    __shared__ unsigned int sm_last;

    const int tid  = threadIdx.x;
    const int j    = tid >> 1;       // label 0..63
    const int h    = tid & 1;        // which i-half of the dot
    const int lane = tid & 31;
    const int wid  = tid >> 5;

    const int b = blockIdx.x;
    const float* emb  = emission + (size_t)b * TT * LL;
    const int*   tgt  = target   + (size_t)b * TT;
    const float* mrow = mask     + (size_t)b * TT;

    // stage (mask, end_mask)
    for (int t = tid; t < TT; t += NTHR) {
        float m  = mrow[t];
        float nm = (t + 1 < TT) ? mrow[t + 1] : 0.0f;
        sm_me[t] = make_float2(m, (m > nm) ? 1.0f : 0.0f);
    }

    // E half-column: E[i][j] = exp(trans[i][j]), i in [32h, 32h+32)
    float E[32];
    #pragma unroll
    for (int i = 0; i < 32; i++)
        E[i] = __expf(trans[(32 * h + i) * LL + j]);
    __syncthreads();

    // ---------------- path score: reduction over t ----------------
    float pacc = 0.0f;
    for (int t = 1 + tid; t < TT; t += NTHR) {
        const int    tp = tgt[t - 1];
        const int    tc = tgt[t];
        const float2 me = sm_me[t];
        pacc += me.x * (trans[tp * LL + tc] + emb[(size_t)t * LL + tc])
              + me.y * end_trans[tc];
    }
    if (tid == 0) {
        const int t0 = tgt[0];
        pacc += start_trans[t0] + emb[t0];
    }
    #pragma unroll
    for (int o = 16; o; o >>= 1) pacc += __shfl_xor_sync(0xffffffffu, pacc, o);
    if (lane == 0) sm_w[wid] = pacc;
    __syncthreads();
    const float path_score = (sm_w[0] + sm_w[1]) + (sm_w[2] + sm_w[3]);

    // ---------------- forward recursion ----------------
    const float et = end_trans[j];
    float s = start_trans[j] + emb[j];           // t = 0 (both h redundantly)

    if (tid == 0) sm_s0[1] = s;
    __syncthreads();
    float S = sm_s0[1];                          // block-uniform lagged shift

    // emission prefetch, distance 2
    float em1 = emb[1 * LL + j];
    float em2 = emb[2 * LL + j];

    for (int t = 1; t < TT; t++) {
        const int   buf    = t & 1;
        const float em_cur = em1;
        em1 = em2;
        if (t + 2 < TT) em2 = emb[(size_t)(t + 2) * LL + j];

        if (tid == 0) sm_s0[buf] = s;            // next iteration's shift
        const float p = __expf(s - S);           // stabilized prob
        if (h == 0) sm_p[buf][j + ((j >> 5) << 2)] = p;   // pad +4 for j>=32
        __syncthreads();

        // partial_h = sum_{i in half h} p_i * E[i][j]   (32 MACs, 8 chains)
        const float4* p4 = (const float4*)sm_p[buf] + 9 * h;  // h=1: float idx 36
        float a0 = 0.f, a1 = 0.f, a2 = 0.f, a3 = 0.f;
        float a4 = 0.f, a5 = 0.f, a6 = 0.f, a7 = 0.f;
        #pragma unroll
        for (int k = 0; k < 4; k++) {
            const float4 vA = p4[2 * k];
            const float4 vB = p4[2 * k + 1];
            a0 += vA.x * E[8 * k + 0];
            a1 += vA.y * E[8 * k + 1];
            a2 += vA.z * E[8 * k + 2];
            a3 += vA.w * E[8 * k + 3];
            a4 += vB.x * E[8 * k + 4];
            a5 += vB.y * E[8 * k + 5];
            a6 += vB.z * E[8 * k + 6];
            a7 += vB.w * E[8 * k + 7];
        }
        const float partial = ((a0 + a1) + (a2 + a3)) + ((a4 + a5) + (a6 + a7));
        const float dot = partial + __shfl_xor_sync(0xffffffffu, partial, 1);

        const float2 me  = sm_me[t];
        const float  nxt = S + __logf(dot) + em_cur;
        s = me.x * nxt + (1.0f - me.x) * s + me.y * et;

        S = sm_s0[buf];
    }

    // normalizer = logsumexp_j(s); each s_j appears twice -> halve the sum
    float wm = s;
    #pragma unroll
    for (int o = 16; o; o >>= 1) wm = fmaxf(wm, __shfl_xor_sync(0xffffffffu, wm, o));
    if (lane == 0) sm_w[wid] = wm;
    __syncthreads();
    const float M = fmaxf(fmaxf(sm_w[0], sm_w[1]), fmaxf(sm_w[2], sm_w[3]));
    float pe = __expf(s - M);
    #pragma unroll
    for (int o = 16; o; o >>= 1) pe += __shfl_xor_sync(0xffffffffu, pe, o);
    if (lane == 0) sm_w2[wid] = pe;
    __syncthreads();

    // ---------------- fused deterministic finalization ----------------
    if (tid == 0) {
        const float tot  = (sm_w2[0] + sm_w2[1]) + (sm_w2[2] + sm_w2[3]);
        const float norm = M + __logf(tot * 0.5f);
        g_res[b] = norm - path_score;
        __threadfence();
        sm_last = atomicAdd(&g_done, 1u);        // BB-1 for the last CTA
    }
    __syncthreads();
    if (sm_last == BB - 1) {
        __threadfence();                         // acquire all g_res
        float acc = (g_res[tid] + g_res[tid + 128])
                  + (g_res[tid + 256] + g_res[tid + 384]);
        #pragma unroll
        for (int o = 16; o; o >>= 1) acc += __shfl_xor_sync(0xffffffffu, acc, o);
        if (lane == 0) sm_w[wid] = acc;
        __syncthreads();
        if (tid == 0) {
            out[0] = ((sm_w[0] + sm_w[1]) + (sm_w[2] + sm_w[3])) * (1.0f / BB);
            g_done = 0;                          // reset for graph replay
        }
    }
}

extern "C" void kernel_launch(void* const* d_in, const int* in_sizes, int n_in,
                              void* d_out, int out_size) {
    const float* emission    = (const float*)d_in[0];
    const int*   target      = (const int*)  d_in[1];
    const float* mask        = (const float*)d_in[2];
    const float* start_trans = (const float*)d_in[3];
    const float* trans       = (const float*)d_in[4];
    const float* end_trans   = (const float*)d_in[5];
    float* out = (float*)d_out;

    crf_main_kernel<<<BB, NTHR>>>(emission, target, mask, start_trans, trans,
                                  end_trans, out);
}